// round 16
// baseline (speedup 1.0000x reference)
#include <cuda_runtime.h>
#include <cuda_bf16.h>
#include <mma.h>
#include <math.h>
#include <stdint.h>

using namespace nvcuda;

#define B_ 32
#define T_ 128

typedef unsigned long long u64t;

// ---------------- device globals ----------------
__device__ float d_M[4 * 4096];
__device__ float d_out0[B_ * T_ * 4096];
__device__ float d_last[B_ * 4096];
__device__ float d_Gx[(size_t)B_ * T_ * 64 * 128];
__device__ float d_Cx[(size_t)B_ * T_ * 64 * 64];
__device__ __align__(16) unsigned char d_MI[2 * 32768];      // [prec][256x64 bf16]
__device__ __align__(16) unsigned char d_WI[2 * 2 * 122880]; // [layer][prec][320x192 bf16]

// ---------------- helpers ----------------
__device__ __forceinline__ u64t pack_dup(float x) {
    u64t r; asm("mov.b64 %0, {%1,%1};" : "=l"(r) : "f"(x)); return r;
}
__device__ __forceinline__ u64t pack2(float lo, float hi) {
    u64t r; asm("mov.b64 %0, {%1,%2};" : "=l"(r) : "f"(lo), "f"(hi)); return r;
}
__device__ __forceinline__ float2 unpack2(u64t v) {
    float2 f; asm("mov.b64 {%0,%1}, %2;" : "=f"(f.x), "=f"(f.y) : "l"(v)); return f;
}
__device__ __forceinline__ void fma2(u64t& d, u64t a, u64t b) {
    asm("fma.rn.f32x2 %0, %1, %2, %0;" : "+l"(d) : "l"(a), "l"(b));
}
__device__ __forceinline__ uint32_t s_u32(const void* p) {
    return (uint32_t)__cvta_generic_to_shared(p);
}
__device__ __forceinline__ uint32_t mapa_rank(uint32_t a, uint32_t r) {
    uint32_t o;
    asm("mapa.shared::cluster.u32 %0, %1, %2;" : "=r"(o) : "r"(a), "r"(r));
    return o;
}
__device__ __forceinline__ float ldc_f32(uint32_t a) {
    float v;
    asm volatile("ld.shared::cluster.f32 %0, [%1];" : "=f"(v) : "r"(a));
    return v;
}
__device__ __forceinline__ void cp16(void* dst, const void* src) {
    asm volatile("cp.async.cg.shared.global [%0], [%1], 16;"
                 :: "r"(s_u32(dst)), "l"(src));
}
#define CP_COMMIT() asm volatile("cp.async.commit_group;")
#define CP_WAIT0()  asm volatile("cp.async.wait_group 0;")
#define CP_WAIT1()  asm volatile("cp.async.wait_group 1;")
#define CLUSTER_ARRIVE() asm volatile("barrier.cluster.arrive.aligned;" ::: "memory")
#define CLUSTER_WAIT()   asm volatile("barrier.cluster.wait.aligned;"   ::: "memory")
#define CLUSTER_SYNC() do { CLUSTER_ARRIVE(); CLUSTER_WAIT(); } while (0)

__device__ __forceinline__ float sigmoid_f(float v) {
    return __fdividef(1.f, 1.f + __expf(-v));
}
__device__ __forceinline__ float tanh_f(float v) {
    return 1.f - __fdividef(2.f, __expf(2.f * v) + 1.f);
}

extern __shared__ float smem[];

// ---------------------------------------------------------------------------
__global__ void prep_kernel(const float* __restrict__ S0, const float* __restrict__ S1)
{
    __shared__ float Ss[64 * 64];
    const int s = blockIdx.x;
    const float* S = s ? S1 : S0;
    for (int i = threadIdx.x; i < 4096; i += blockDim.x) Ss[i] = S[i];
    __syncthreads();
    for (int i = threadIdx.x; i < 4096; i += blockDim.x) {
        int m = i >> 6, n = i & 63;
        float acc = 0.f;
        #pragma unroll 8
        for (int p = 0; p < 64; ++p) acc += Ss[m * 64 + p] * Ss[p * 64 + n];
        d_M[(2 * s) * 4096 + i]     = Ss[i];
        d_M[(2 * s + 1) * 4096 + i] = 2.f * acc - (m == n ? 1.f : 0.f);
    }
}

// ---------------------------------------------------------------------------
__global__ void prep_img(const float* __restrict__ Wg0, const float* __restrict__ Wc0,
                         const float* __restrict__ Wg1, const float* __restrict__ Wc1)
{
    const int gt = blockIdx.x * blockDim.x + threadIdx.x;
    const int gs = gridDim.x * blockDim.x;
    for (int i = gt; i < 16384; i += gs) {
        int np = i >> 6, n = i & 63;
        float v = d_M[(np >> 6) * 4096 + (np & 63) * 64 + n];
        __nv_bfloat16 hi = __float2bfloat16(v);
        __nv_bfloat16 lo = __float2bfloat16(v - __bfloat162float(hi));
        *(__nv_bfloat16*)(d_MI + np * 128 + n * 2) = hi;
        *(__nv_bfloat16*)(d_MI + 32768 + np * 128 + n * 2) = lo;
    }
    for (int i = gt; i < 2 * 61440; i += gs) {
        int l = i / 61440, rem = i % 61440;
        int kcat = rem / 192, c = rem % 192;
        int kt = kcat >> 6, kk = kcat & 63;
        float v;
        if (c < 128) v = (l ? Wg1 : Wg0)[(size_t)(kt * 128 + kk) * 128 + c];
        else         v = (l ? Wc1 : Wc0)[(size_t)(kt * 128 + kk) * 64 + (c - 128)];
        __nv_bfloat16 hi = __float2bfloat16(v);
        __nv_bfloat16 lo = __float2bfloat16(v - __bfloat162float(hi));
        unsigned char* base = d_WI + l * 245760;
        *(__nv_bfloat16*)(base + kcat * 384 + c * 2) = hi;
        *(__nv_bfloat16*)(base + 122880 + kcat * 384 + c * 2) = lo;
    }
}

// ---------------------------------------------------------------------------
// WMMA precompute of Gx/Cx (R14, unchanged).
// ---------------------------------------------------------------------------
#define PRE2_SMEM (83968 + 102400)

__global__ void __launch_bounds__(256, 1)
pre_wmma(const float* __restrict__ Xin, const float* __restrict__ bg,
         const float* __restrict__ bc, int layer)
{
    unsigned char* sm  = (unsigned char*)smem;
    __nv_bfloat16* A2h = (__nv_bfloat16*)sm;
    __nv_bfloat16* A2l = (__nv_bfloat16*)(sm + 41984);
    unsigned char* SCR = sm + 83968;

    const int tid = threadIdx.x;
    const int w = tid >> 5;
    const int bt = blockIdx.x;

    for (int i = tid; i < 4096; i += 256) {
        int prec = i >> 11, r2 = i & 2047, row = r2 >> 3, c = r2 & 7;
        cp16(SCR + prec * 36864 + row * 144 + c * 16,
             d_MI + prec * 32768 + row * 128 + c * 16);
    }
    CP_COMMIT();
    const float* xsrc = (layer ? d_out0 : Xin) + (size_t)bt * 4096;
    for (int i = tid; i < 4096; i += 256) {
        int n = i >> 6, f = i & 63;
        float v = xsrc[i];
        __nv_bfloat16 hi = __float2bfloat16(v);
        __nv_bfloat16 lo = __float2bfloat16(v - __bfloat162float(hi));
        A2h[n * 328 + f] = hi;
        A2l[n * 328 + f] = lo;
    }
    CP_WAIT0();
    __syncthreads();

    {
        wmma::fragment<wmma::accumulator, 16, 16, 16, float> acc1[8];
        #pragma unroll
        for (int i = 0; i < 8; ++i) wmma::fill_fragment(acc1[i], 0.f);
        const __nv_bfloat16* Mh = (const __nv_bfloat16*)SCR;
        const __nv_bfloat16* Ml = (const __nv_bfloat16*)(SCR + 36864);
        #pragma unroll
        for (int ks = 0; ks < 4; ++ks) {
            wmma::fragment<wmma::matrix_a, 16, 16, 16, __nv_bfloat16, wmma::row_major> ah[2], al[2];
            wmma::fragment<wmma::matrix_b, 16, 16, 16, __nv_bfloat16, wmma::row_major> bh[4], bl[4];
            #pragma unroll
            for (int mi = 0; mi < 2; ++mi) {
                wmma::load_matrix_sync(ah[mi], Mh + (w * 2 + mi) * 16 * 72 + ks * 16, 72);
                wmma::load_matrix_sync(al[mi], Ml + (w * 2 + mi) * 16 * 72 + ks * 16, 72);
            }
            #pragma unroll
            for (int nt = 0; nt < 4; ++nt) {
                wmma::load_matrix_sync(bh[nt], A2h + ks * 16 * 328 + nt * 16, 328);
                wmma::load_matrix_sync(bl[nt], A2l + ks * 16 * 328 + nt * 16, 328);
            }
            #pragma unroll
            for (int mi = 0; mi < 2; ++mi)
                #pragma unroll
                for (int nt = 0; nt < 4; ++nt) {
                    int x = mi * 4 + nt;
                    wmma::mma_sync(acc1[x], ah[mi], bh[nt], acc1[x]);
                    wmma::mma_sync(acc1[x], al[mi], bh[nt], acc1[x]);
                    wmma::mma_sync(acc1[x], ah[mi], bl[nt], acc1[x]);
                }
        }
        __syncthreads();
        float* S = (float*)SCR;
        #pragma unroll
        for (int mi = 0; mi < 2; ++mi)
            #pragma unroll
            for (int nt = 0; nt < 4; ++nt)
                wmma::store_matrix_sync(S + (w * 2 + mi) * 16 * 72 + nt * 16,
                                        acc1[mi * 4 + nt], 72, wmma::mem_row_major);
        __syncthreads();
        for (int i = tid; i < 16384; i += 256) {
            int row = i >> 6, f = i & 63;
            int k = row >> 6, m = row & 63;
            float v = S[row * 72 + f];
            __nv_bfloat16 hi = __float2bfloat16(v);
            __nv_bfloat16 lo = __float2bfloat16(v - __bfloat162float(hi));
            A2h[m * 328 + (k + 1) * 64 + f] = hi;
            A2l[m * 328 + (k + 1) * 64 + f] = lo;
        }
        __syncthreads();
    }

    {
        wmma::fragment<wmma::accumulator, 16, 16, 16, float> acc2[6];
        #pragma unroll
        for (int i = 0; i < 6; ++i) wmma::fill_fragment(acc2[i], 0.f);
        const int mt = w >> 1, ng = w & 1;
        const unsigned char* gW = d_WI + layer * 245760;

        {
            unsigned char* dst = SCR;
            for (int i = tid; i < 1536; i += 256) {
                int row = i / 24, c = i % 24;
                cp16(dst + row * 400 + c * 16, gW + row * 384 + c * 16);
                cp16(dst + 25600 + row * 400 + c * 16, gW + 122880 + row * 384 + c * 16);
            }
            CP_COMMIT();
        }

        for (int kt = 0; kt < 5; ++kt) {
            if (kt < 4) {
                unsigned char* dst = SCR + ((kt + 1) & 1) * 51200;
                const unsigned char* srcH = gW + (kt + 1) * 24576;
                const unsigned char* srcL = gW + 122880 + (kt + 1) * 24576;
                for (int i = tid; i < 1536; i += 256) {
                    int row = i / 24, c = i % 24;
                    cp16(dst + row * 400 + c * 16, srcH + row * 384 + c * 16);
                    cp16(dst + 25600 + row * 400 + c * 16, srcL + row * 384 + c * 16);
                }
            }
            CP_COMMIT();
            CP_WAIT1();
            __syncthreads();

            const __nv_bfloat16* WbH = (const __nv_bfloat16*)(SCR + (kt & 1) * 51200);
            const __nv_bfloat16* WbL = (const __nv_bfloat16*)(SCR + (kt & 1) * 51200 + 25600);
            #pragma unroll
            for (int ks = 0; ks < 4; ++ks) {
                wmma::fragment<wmma::matrix_a, 16, 16, 16, __nv_bfloat16, wmma::row_major> ah, al;
                wmma::load_matrix_sync(ah, A2h + mt * 16 * 328 + kt * 64 + ks * 16, 328);
                wmma::load_matrix_sync(al, A2l + mt * 16 * 328 + kt * 64 + ks * 16, 328);
                #pragma unroll
                for (int nt = 0; nt < 6; ++nt) {
                    wmma::fragment<wmma::matrix_b, 16, 16, 16, __nv_bfloat16, wmma::row_major> bh, bl;
                    int nc = (ng * 6 + nt) * 16;
                    wmma::load_matrix_sync(bh, WbH + ks * 16 * 200 + nc, 200);
                    wmma::load_matrix_sync(bl, WbL + ks * 16 * 200 + nc, 200);
                    wmma::mma_sync(acc2[nt], ah, bh, acc2[nt]);
                    wmma::mma_sync(acc2[nt], al, bh, acc2[nt]);
                    wmma::mma_sync(acc2[nt], ah, bl, acc2[nt]);
                }
            }
            __syncthreads();
        }

        float* S = (float*)SCR;
        #pragma unroll
        for (int nt = 0; nt < 6; ++nt)
            wmma::store_matrix_sync(S + mt * 16 * 200 + (ng * 6 + nt) * 16,
                                    acc2[nt], 200, wmma::mem_row_major);
        __syncthreads();
        for (int i = tid; i < 12288; i += 256) {
            int n = i / 192, c = i % 192;
            float v = S[n * 200 + c];
            if (c < 128) d_Gx[(size_t)bt * 8192 + n * 128 + c] = v + bg[c];
            else         d_Cx[(size_t)bt * 4096 + n * 64 + (c - 128)] = v + bc[c - 128];
        }
    }
}

// ---------------------------------------------------------------------------
// Scan v8: wmma V-phases + warp-specialized overlap:
//   r-half gate M-apply first (k-split, all warps); after r-exchange,
//   warps 0-7 run cand V wmma (tensor) into Vs cols k*32+0..15 (freed by
//   r-half) WHILE warps 8-15 run the u-half gate M-apply (fma) reading
//   Vs cols k*32+16..31. Cand M-apply reads Vk at k*32.
// smem: WIh 0(33792) WIl 33792(33792) Ms 67584(69632) Vs 137216(41984)
//   hH 179200(9216) hL 188416(9216) h_loc 197632(4352) rst 201984(4352)
//   ugs 206336(4352) hst 210688(4352) yP 215040(4096) total 219136
// ---------------------------------------------------------------------------
#define SCAN_SMEM_BYTES 219136

__global__ void __launch_bounds__(512, 1) __cluster_dims__(4, 1, 1)
scan_kernel(const float* __restrict__ Wg, const float* __restrict__ Wc,
            const int* __restrict__ lens, int layer)
{
    unsigned char* sm = (unsigned char*)smem;
    __nv_bfloat16* WIh = (__nv_bfloat16*)sm;            // [64 d][264] gate 0..159, cand 160..239
    __nv_bfloat16* WIl = (__nv_bfloat16*)(sm + 33792);
    float* Ms    = (float*)(sm + 67584);                // 4 x [64][68]
    float* Vs    = (float*)(sm + 137216);               // [64][164]
    __nv_bfloat16* hH = (__nv_bfloat16*)(sm + 179200);  // [64][72]
    __nv_bfloat16* hL = (__nv_bfloat16*)(sm + 188416);
    float* h_loc = (float*)(sm + 197632);               // [64][17]
    float* rst   = (float*)(sm + 201984);
    float* ugs   = (float*)(sm + 206336);
    float* hst   = (float*)(sm + 210688);
    float* yP    = (float*)(sm + 215040);               // 1024 floats

    const int tid = threadIdx.x;
    const int w   = tid >> 5;
    const int b = blockIdx.x >> 2;
    const int j = blockIdx.x & 3;

    for (int i = tid; i < 64 * 240; i += 512) {
        int d = i / 240, o = i % 240;
        float v;
        if (o < 160) {
            int k = o >> 5, c = o & 31;
            int g = (c < 16) ? (j * 16 + c) : (64 + j * 16 + (c - 16));
            v = Wg[(size_t)(k * 128 + 64 + d) * 128 + g];
        } else {
            int oc = o - 160, k = oc >> 4, c = oc & 15;
            v = Wc[(size_t)(k * 128 + 64 + d) * 64 + j * 16 + c];
        }
        __nv_bfloat16 hi = __float2bfloat16(v);
        __nv_bfloat16 lo = __float2bfloat16(v - __bfloat162float(hi));
        WIh[d * 264 + o] = hi;
        WIl[d * 264 + o] = lo;
    }
    for (int i = tid; i < 16384; i += 512) {
        int k = i >> 12, r = (i >> 6) & 63, p = i & 63;
        Ms[k * 4352 + r * 68 + p] = d_M[i];
    }
    for (int i = tid; i < 4096; i += 512) {
        int n = i >> 6, d = i & 63;
        hH[n * 72 + d] = __float2bfloat16(0.f);
        hL[n * 72 + d] = __float2bfloat16(0.f);
        if (d < 17) h_loc[n * 17 + d] = 0.f;
    }

    int idx_t = lens[b] - 1;
    idx_t = idx_t < 0 ? 0 : (idx_t > T_ - 1 ? T_ - 1 : idx_t);

    uint32_t rbase[4], hbase[4];
    #pragma unroll
    for (int r = 0; r < 4; ++r) {
        rbase[r] = mapa_rank(s_u32(rst), (uint32_t)r);
        hbase[r] = mapa_rank(s_u32(hst), (uint32_t)r);
    }

    const int dh  = tid >> 8;
    const int s5  = tid & 255;
    const int mg  = s5 >> 3;
    const int ja2 = (s5 & 7) * 2;
    const u64t ONE = pack_dup(1.f);
    const int en0 = tid >> 4, edl = tid & 15;
    const uint32_t eoff0 = (uint32_t)(en0 * 17 + edl) * 4;
    const uint32_t eoff1 = (uint32_t)((en0 + 32) * 17 + edl) * 4;
    const int rt = w & 3;

    const float* gxb = d_Gx + (size_t)b * T_ * 8192;
    const float* cxb = d_Cx + (size_t)b * T_ * 4096;

    for (int t = 0; t < T_; ++t) {
        __syncthreads();

        const float* gx = gxb + (size_t)t * 8192;
        const float* cx = cxb + (size_t)t * 4096;
        float2 gR0 = make_float2(0.f, 0.f), gR1 = gR0;
        float2 cA = gR0, cB = gR0;
        if (dh == 0) {
            gR0 = __ldg((const float2*)(gx + mg * 128 + j * 16 + ja2));
            gR1 = __ldg((const float2*)(gx + (mg + 32) * 128 + j * 16 + ja2));
            cA  = __ldg((const float2*)(cx + mg * 64 + j * 16 + ja2));
            cB  = __ldg((const float2*)(cx + (mg + 32) * 64 + j * 16 + ja2));
        }

        // ---------- gate V-phase: wmma, all 16 warps, 40 tiles ----------
        {
            wmma::fragment<wmma::matrix_a, 16, 16, 16, __nv_bfloat16, wmma::row_major> a_h[4], a_l[4];
            #pragma unroll
            for (int kf = 0; kf < 4; ++kf) {
                wmma::load_matrix_sync(a_h[kf], hH + rt * 16 * 72 + kf * 16, 72);
                wmma::load_matrix_sync(a_l[kf], hL + rt * 16 * 72 + kf * 16, 72);
            }
            for (int tile = w; tile < 40; tile += 16) {
                int ct = tile >> 2;
                wmma::fragment<wmma::accumulator, 16, 16, 16, float> acc;
                wmma::fill_fragment(acc, 0.f);
                #pragma unroll
                for (int kf = 0; kf < 4; ++kf) {
                    wmma::fragment<wmma::matrix_b, 16, 16, 16, __nv_bfloat16, wmma::row_major> bh, bl;
                    wmma::load_matrix_sync(bh, WIh + kf * 16 * 264 + ct * 16, 264);
                    wmma::load_matrix_sync(bl, WIl + kf * 16 * 264 + ct * 16, 264);
                    wmma::mma_sync(acc, a_h[kf], bh, acc);
                    wmma::mma_sync(acc, a_l[kf], bh, acc);
                    wmma::mma_sync(acc, a_h[kf], bl, acc);
                }
                wmma::store_matrix_sync(Vs + rt * 16 * 164 + ct * 16, acc, 164, wmma::mem_row_major);
            }
        }
        __syncthreads();

        // ---------- gate M-apply, r-half only (k-split) + sigmoid -> rst ----------
        {
            u64t y0, y1;
            if (dh == 0) {
                float2 v0 = *(const float2*)(Vs + mg * 164 + ja2);
                float2 v1 = *(const float2*)(Vs + (mg + 32) * 164 + ja2);
                y0 = pack2(gR0.x + v0.x, gR0.y + v0.y);
                y1 = pack2(gR1.x + v1.x, gR1.y + v1.y);
            } else {
                y0 = y1 = pack_dup(0.f);
            }
            const int kb = 1 + dh * 2;
            #pragma unroll
            for (int kk = 0; kk < 2; ++kk) {
                const float* Mk = Ms + (kb - 1 + kk) * 4352;
                const float* Vk = Vs + (kb + kk) * 32;
                #pragma unroll 4
                for (int m = 0; m < 64; m += 4) {
                    float4 mA = *(const float4*)(Mk + mg * 68 + m);
                    float4 mB = *(const float4*)(Mk + (mg + 32) * 68 + m);
                    float mAa[4] = {mA.x, mA.y, mA.z, mA.w};
                    float mBa[4] = {mB.x, mB.y, mB.z, mB.w};
                    #pragma unroll
                    for (int q = 0; q < 4; ++q) {
                        u64t v = *(const u64t*)(Vk + (m + q) * 164 + ja2);
                        fma2(y0, pack_dup(mAa[q]), v);
                        fma2(y1, pack_dup(mBa[q]), v);
                    }
                }
            }
            if (dh == 1) {
                *(u64t*)(yP + s5 * 4)     = y0;
                *(u64t*)(yP + s5 * 4 + 2) = y1;
            }
            __syncthreads();
            if (dh == 0) {
                u64t pa = *(const u64t*)(yP + s5 * 4);
                u64t pb = *(const u64t*)(yP + s5 * 4 + 2);
                fma2(y0, ONE, pa);
                fma2(y1, ONE, pb);
                float2 p0 = unpack2(y0), p1 = unpack2(y1);
                rst[mg * 17 + ja2]            = sigmoid_f(p0.x);
                rst[mg * 17 + ja2 + 1]        = sigmoid_f(p0.y);
                rst[(mg + 32) * 17 + ja2]     = sigmoid_f(p1.x);
                rst[(mg + 32) * 17 + ja2 + 1] = sigmoid_f(p1.y);
            }
        }

        // r exchange; rh = r*(hH+hL) back into hH/hL split
        CLUSTER_ARRIVE();
        __syncthreads();
        {
            int d = j * 16 + edl;
            #pragma unroll
            for (int half = 0; half < 2; ++half) {
                int n = en0 + half * 32;
                float hv = __bfloat162float(hH[n * 72 + d]) + __bfloat162float(hL[n * 72 + d]);
                float rh = rst[n * 17 + edl] * hv;
                __nv_bfloat16 hi = __float2bfloat16(rh);
                hH[n * 72 + d] = hi;
                hL[n * 72 + d] = __float2bfloat16(rh - __bfloat162float(hi));
            }
        }
        CLUSTER_WAIT();
        {
            float rv[3][2];
            #pragma unroll
            for (int rr = 1; rr < 4; ++rr) {
                uint32_t rb = rbase[(j + rr) & 3];
                rv[rr - 1][0] = ldc_f32(rb + eoff0);
                rv[rr - 1][1] = ldc_f32(rb + eoff1);
            }
            #pragma unroll
            for (int rr = 1; rr < 4; ++rr) {
                int d = ((j + rr) & 3) * 16 + edl;
                #pragma unroll
                for (int half = 0; half < 2; ++half) {
                    int n = en0 + half * 32;
                    float hv = __bfloat162float(hH[n * 72 + d]) + __bfloat162float(hL[n * 72 + d]);
                    float rh = rv[rr - 1][half] * hv;
                    __nv_bfloat16 hi = __float2bfloat16(rh);
                    hH[n * 72 + d] = hi;
                    hL[n * 72 + d] = __float2bfloat16(rh - __bfloat162float(hi));
                }
            }
        }
        __syncthreads();

        // ---------- OVERLAP: warps 0-7 cand V wmma || warps 8-15 u-half M-apply ----------
        if (w < 8) {
            // cand V: 20 tiles into Vs cols k*32 + 0..15 (r-region, now dead)
            wmma::fragment<wmma::matrix_a, 16, 16, 16, __nv_bfloat16, wmma::row_major> a_h[4], a_l[4];
            #pragma unroll
            for (int kf = 0; kf < 4; ++kf) {
                wmma::load_matrix_sync(a_h[kf], hH + rt * 16 * 72 + kf * 16, 72);
                wmma::load_matrix_sync(a_l[kf], hL + rt * 16 * 72 + kf * 16, 72);
            }
            for (int ctk = (w >> 2); ctk < 5; ctk += 2) {
                wmma::fragment<wmma::accumulator, 16, 16, 16, float> acc;
                wmma::fill_fragment(acc, 0.f);
                #pragma unroll
                for (int kf = 0; kf < 4; ++kf) {
                    wmma::fragment<wmma::matrix_b, 16, 16, 16, __nv_bfloat16, wmma::row_major> bh, bl;
                    wmma::load_matrix_sync(bh, WIh + kf * 16 * 264 + 160 + ctk * 16, 264);
                    wmma::load_matrix_sync(bl, WIl + kf * 16 * 264 + 160 + ctk * 16, 264);
                    wmma::mma_sync(acc, a_h[kf], bh, acc);
                    wmma::mma_sync(acc, a_l[kf], bh, acc);
                    wmma::mma_sync(acc, a_h[kf], bl, acc);
                }
                wmma::store_matrix_sync(Vs + rt * 16 * 164 + ctk * 32, acc, 164, wmma::mem_row_major);
            }
        } else {
            // u-half gate M-apply: full 5-k sum, reads Vs cols k*32+16..31
            const int t5 = tid - 256;
            const int mg5 = t5 >> 3;
            const int cu = 16 + (t5 & 7) * 2;
            const int gu = 64 + j * 16 + (t5 & 7) * 2;
            float2 gU0 = __ldg((const float2*)(gx + mg5 * 128 + gu));
            float2 gU1 = __ldg((const float2*)(gx + (mg5 + 32) * 128 + gu));
            float2 v0 = *(const float2*)(Vs + mg5 * 164 + cu);
            float2 v1 = *(const float2*)(Vs + (mg5 + 32) * 164 + cu);
            u64t y0 = pack2(gU0.x + v0.x, gU0.y + v0.y);
            u64t y1 = pack2(gU1.x + v1.x, gU1.y + v1.y);
            #pragma unroll
            for (int k = 1; k < 5; ++k) {
                const float* Mk = Ms + (k - 1) * 4352;
                const float* Vk = Vs + k * 32 + 16;
                #pragma unroll 4
                for (int m = 0; m < 64; m += 4) {
                    float4 mA = *(const float4*)(Mk + mg5 * 68 + m);
                    float4 mB = *(const float4*)(Mk + (mg5 + 32) * 68 + m);
                    float mAa[4] = {mA.x, mA.y, mA.z, mA.w};
                    float mBa[4] = {mB.x, mB.y, mB.z, mB.w};
                    #pragma unroll
                    for (int q = 0; q < 4; ++q) {
                        u64t v = *(const u64t*)(Vk + (m + q) * 164 + (cu - 16));
                        fma2(y0, pack_dup(mAa[q]), v);
                        fma2(y1, pack_dup(mBa[q]), v);
                    }
                }
            }
            float2 p0 = unpack2(y0), p1 = unpack2(y1);
            ugs[mg5 * 17 + cu - 16]            = sigmoid_f(p0.x);
            ugs[mg5 * 17 + cu - 15]            = sigmoid_f(p0.y);
            ugs[(mg5 + 32) * 17 + cu - 16]     = sigmoid_f(p1.x);
            ugs[(mg5 + 32) * 17 + cu - 15]     = sigmoid_f(p1.y);
        }
        __syncthreads();

        // ---------- cand M-apply (k-split, Vk at k*32) + GRU ----------
        {
            u64t y0, y1;
            if (dh == 0) {
                float2 v0 = *(const float2*)(Vs + mg * 164 + ja2);
                float2 v1 = *(const float2*)(Vs + (mg + 32) * 164 + ja2);
                y0 = pack2(cA.x + v0.x, cA.y + v0.y);
                y1 = pack2(cB.x + v1.x, cB.y + v1.y);
            } else {
                y0 = y1 = pack_dup(0.f);
            }
            const int kb = 1 + dh * 2;
            #pragma unroll
            for (int kk = 0; kk < 2; ++kk) {
                const float* Mk = Ms + (kb - 1 + kk) * 4352;
                const float* Vk = Vs + (kb + kk) * 32;
                #pragma unroll 4
                for (int m = 0; m < 64; m += 4) {
                    float4 mA = *(const float4*)(Mk + mg * 68 + m);
                    float4 mB = *(const float4*)(Mk + (mg + 32) * 68 + m);
                    float mAa[4] = {mA.x, mA.y, mA.z, mA.w};
                    float mBa[4] = {mB.x, mB.y, mB.z, mB.w};
                    #pragma unroll
                    for (int q = 0; q < 4; ++q) {
                        u64t v = *(const u64t*)(Vk + (m + q) * 164 + ja2);
                        fma2(y0, pack_dup(mAa[q]), v);
                        fma2(y1, pack_dup(mBa[q]), v);
                    }
                }
            }
            if (dh == 1) {
                *(u64t*)(yP + s5 * 4)     = y0;
                *(u64t*)(yP + s5 * 4 + 2) = y1;
            }
            __syncthreads();
            if (dh == 0) {
                u64t pa = *(const u64t*)(yP + s5 * 4);
                u64t pb = *(const u64t*)(yP + s5 * 4 + 2);
                fma2(y0, ONE, pa);
                fma2(y1, ONE, pb);
                float* hout0 = d_out0 + ((size_t)(b * T_ + t)) * 4096;
                float2 cc0 = unpack2(y0), cc1 = unpack2(y1);
                float cand0[2] = {cc0.x, cc0.y};
                float cand1[2] = {cc1.x, cc1.y};
                #pragma unroll
                for (int q = 0; q < 2; ++q) {
                    int cl = ja2 + q;
                    int col = j * 16 + cl;
                    float cv0 = tanh_f(cand0[q]);
                    float ug0 = ugs[mg * 17 + cl];
                    float hn0 = ug0 * h_loc[mg * 17 + cl] + (1.f - ug0) * cv0;
                    hst[mg * 17 + cl] = hn0;
                    float cv1 = tanh_f(cand1[q]);
                    float ug1 = ugs[(mg + 32) * 17 + cl];
                    float hn1 = ug1 * h_loc[(mg + 32) * 17 + cl] + (1.f - ug1) * cv1;
                    hst[(mg + 32) * 17 + cl] = hn1;
                    if (layer == 0) {
                        hout0[mg * 64 + col]        = hn0;
                        hout0[(mg + 32) * 64 + col] = hn1;
                    } else if (t == idx_t) {
                        d_last[(size_t)b * 4096 + mg * 64 + col]        = hn0;
                        d_last[(size_t)b * 4096 + (mg + 32) * 64 + col] = hn1;
                    }
                }
            }
        }

        // h exchange
        CLUSTER_ARRIVE();
        __syncthreads();
        {
            int d = j * 16 + edl;
            #pragma unroll
            for (int half = 0; half < 2; ++half) {
                int n = en0 + half * 32;
                float hv = hst[n * 17 + edl];
                __nv_bfloat16 hi = __float2bfloat16(hv);
                hH[n * 72 + d] = hi;
                hL[n * 72 + d] = __float2bfloat16(hv - __bfloat162float(hi));
                h_loc[n * 17 + edl] = hv;
            }
        }
        CLUSTER_WAIT();
        {
            float hv[3][2];
            #pragma unroll
            for (int rr = 1; rr < 4; ++rr) {
                uint32_t hb = hbase[(j + rr) & 3];
                hv[rr - 1][0] = ldc_f32(hb + eoff0);
                hv[rr - 1][1] = ldc_f32(hb + eoff1);
            }
            #pragma unroll
            for (int rr = 1; rr < 4; ++rr) {
                int d = ((j + rr) & 3) * 16 + edl;
                #pragma unroll
                for (int half = 0; half < 2; ++half) {
                    int n = en0 + half * 32;
                    float v = hv[rr - 1][half];
                    __nv_bfloat16 hi = __float2bfloat16(v);
                    hH[n * 72 + d] = hi;
                    hL[n * 72 + d] = __float2bfloat16(v - __bfloat162float(hi));
                }
            }
        }
    }
    CLUSTER_SYNC();
}

// ---------------------------------------------------------------------------
__global__ void final_kernel(const float* __restrict__ Wp, const float* __restrict__ bp,
                             float* __restrict__ out)
{
    __shared__ float red[64 * 4];
    const int b = blockIdx.x, n = threadIdx.x;
    const float* h = d_last + (size_t)b * 4096 + n * 64;
    float l0 = bp[0], l1 = bp[1], l2 = bp[2], l3 = bp[3];
    #pragma unroll 8
    for (int d = 0; d < 64; ++d) {
        float v = fmaxf(h[d], 0.f);
        l0 += v * Wp[d * 4 + 0];
        l1 += v * Wp[d * 4 + 1];
        l2 += v * Wp[d * 4 + 2];
        l3 += v * Wp[d * 4 + 3];
    }
    red[n * 4 + 0] = l0; red[n * 4 + 1] = l1; red[n * 4 + 2] = l2; red[n * 4 + 3] = l3;
    __syncthreads();
    for (int s = 32; s > 0; s >>= 1) {
        if (n < s) {
            #pragma unroll
            for (int c = 0; c < 4; ++c)
                red[n * 4 + c] = fmaxf(red[n * 4 + c], red[(n + s) * 4 + c]);
        }
        __syncthreads();
    }
    if (n < 4) out[b * 4 + n] = red[n];
}

// ---------------------------------------------------------------------------
extern "C" void kernel_launch(void* const* d_in, const int* in_sizes, int n_in,
                              void* d_out, int out_size)
{
    (void)in_sizes; (void)n_in; (void)out_size;
    const float* X   = (const float*)d_in[0];
    const int*   len = (const int*)  d_in[1];
    const float* S0  = (const float*)d_in[2];
    const float* S1  = (const float*)d_in[3];
    const float* Wg0 = (const float*)d_in[4];
    const float* bg0 = (const float*)d_in[5];
    const float* Wc0 = (const float*)d_in[6];
    const float* bc0 = (const float*)d_in[7];
    const float* Wg1 = (const float*)d_in[8];
    const float* bg1 = (const float*)d_in[9];
    const float* Wc1 = (const float*)d_in[10];
    const float* bc1 = (const float*)d_in[11];
    const float* Wp  = (const float*)d_in[12];
    const float* bp  = (const float*)d_in[13];
    float* out = (float*)d_out;

    cudaFuncSetAttribute(pre_wmma,    cudaFuncAttributeMaxDynamicSharedMemorySize, PRE2_SMEM);
    cudaFuncSetAttribute(scan_kernel, cudaFuncAttributeMaxDynamicSharedMemorySize, SCAN_SMEM_BYTES);

    prep_kernel<<<2, 256>>>(S0, S1);
    prep_img<<<64, 256>>>(Wg0, Wc0, Wg1, Wc1);
    pre_wmma<<<B_ * T_, 256, PRE2_SMEM>>>(X, bg0, bc0, 0);
    scan_kernel<<<128, 512, SCAN_SMEM_BYTES>>>(Wg0, Wc0, len, 0);
    pre_wmma<<<B_ * T_, 256, PRE2_SMEM>>>(X, bg1, bc1, 1);
    scan_kernel<<<128, 512, SCAN_SMEM_BYTES>>>(Wg1, Wc1, len, 1);
    final_kernel<<<B_, 64>>>(Wp, bp, out);
}

// round 17
// speedup vs baseline: 1.0791x; 1.0791x over previous
#include <cuda_runtime.h>
#include <cuda_bf16.h>
#include <mma.h>
#include <math.h>
#include <stdint.h>

using namespace nvcuda;

#define B_ 32
#define T_ 128

typedef unsigned long long u64t;

// ---------------- device globals ----------------
__device__ float d_M[4 * 4096];
__device__ float d_out0[B_ * T_ * 4096];
__device__ float d_last[B_ * 4096];
__device__ float d_Gx[(size_t)B_ * T_ * 64 * 128];
__device__ float d_Cx[(size_t)B_ * T_ * 64 * 64];
__device__ __align__(16) unsigned char d_MI[2 * 32768];      // [prec][256x64 bf16]
__device__ __align__(16) unsigned char d_WI[2 * 2 * 122880]; // [layer][prec][320x192 bf16]

// ---------------- helpers ----------------
__device__ __forceinline__ u64t pack_dup(float x) {
    u64t r; asm("mov.b64 %0, {%1,%1};" : "=l"(r) : "f"(x)); return r;
}
__device__ __forceinline__ u64t pack2(float lo, float hi) {
    u64t r; asm("mov.b64 %0, {%1,%2};" : "=l"(r) : "f"(lo), "f"(hi)); return r;
}
__device__ __forceinline__ float2 unpack2(u64t v) {
    float2 f; asm("mov.b64 {%0,%1}, %2;" : "=f"(f.x), "=f"(f.y) : "l"(v)); return f;
}
__device__ __forceinline__ void fma2(u64t& d, u64t a, u64t b) {
    asm("fma.rn.f32x2 %0, %1, %2, %0;" : "+l"(d) : "l"(a), "l"(b));
}
__device__ __forceinline__ uint32_t s_u32(const void* p) {
    return (uint32_t)__cvta_generic_to_shared(p);
}
__device__ __forceinline__ uint32_t mapa_rank(uint32_t a, uint32_t r) {
    uint32_t o;
    asm("mapa.shared::cluster.u32 %0, %1, %2;" : "=r"(o) : "r"(a), "r"(r));
    return o;
}
__device__ __forceinline__ float ldc_f32(uint32_t a) {
    float v;
    asm volatile("ld.shared::cluster.f32 %0, [%1];" : "=f"(v) : "r"(a));
    return v;
}
__device__ __forceinline__ void cp16(void* dst, const void* src) {
    asm volatile("cp.async.cg.shared.global [%0], [%1], 16;"
                 :: "r"(s_u32(dst)), "l"(src));
}
#define CP_COMMIT() asm volatile("cp.async.commit_group;")
#define CP_WAIT0()  asm volatile("cp.async.wait_group 0;")
#define CP_WAIT1()  asm volatile("cp.async.wait_group 1;")
#define CLUSTER_ARRIVE() asm volatile("barrier.cluster.arrive.aligned;" ::: "memory")
#define CLUSTER_WAIT()   asm volatile("barrier.cluster.wait.aligned;"   ::: "memory")
#define CLUSTER_SYNC() do { CLUSTER_ARRIVE(); CLUSTER_WAIT(); } while (0)

__device__ __forceinline__ float sigmoid_f(float v) {
    return __fdividef(1.f, 1.f + __expf(-v));
}
__device__ __forceinline__ float tanh_f(float v) {
    return 1.f - __fdividef(2.f, __expf(2.f * v) + 1.f);
}

extern __shared__ float smem[];

// ---------------------------------------------------------------------------
__global__ void prep_kernel(const float* __restrict__ S0, const float* __restrict__ S1)
{
    __shared__ float Ss[64 * 64];
    const int s = blockIdx.x;
    const float* S = s ? S1 : S0;
    for (int i = threadIdx.x; i < 4096; i += blockDim.x) Ss[i] = S[i];
    __syncthreads();
    for (int i = threadIdx.x; i < 4096; i += blockDim.x) {
        int m = i >> 6, n = i & 63;
        float acc = 0.f;
        #pragma unroll 8
        for (int p = 0; p < 64; ++p) acc += Ss[m * 64 + p] * Ss[p * 64 + n];
        d_M[(2 * s) * 4096 + i]     = Ss[i];
        d_M[(2 * s + 1) * 4096 + i] = 2.f * acc - (m == n ? 1.f : 0.f);
    }
}

// ---------------------------------------------------------------------------
__global__ void prep_img(const float* __restrict__ Wg0, const float* __restrict__ Wc0,
                         const float* __restrict__ Wg1, const float* __restrict__ Wc1)
{
    const int gt = blockIdx.x * blockDim.x + threadIdx.x;
    const int gs = gridDim.x * blockDim.x;
    for (int i = gt; i < 16384; i += gs) {
        int np = i >> 6, n = i & 63;
        float v = d_M[(np >> 6) * 4096 + (np & 63) * 64 + n];
        __nv_bfloat16 hi = __float2bfloat16(v);
        __nv_bfloat16 lo = __float2bfloat16(v - __bfloat162float(hi));
        *(__nv_bfloat16*)(d_MI + np * 128 + n * 2) = hi;
        *(__nv_bfloat16*)(d_MI + 32768 + np * 128 + n * 2) = lo;
    }
    for (int i = gt; i < 2 * 61440; i += gs) {
        int l = i / 61440, rem = i % 61440;
        int kcat = rem / 192, c = rem % 192;
        int kt = kcat >> 6, kk = kcat & 63;
        float v;
        if (c < 128) v = (l ? Wg1 : Wg0)[(size_t)(kt * 128 + kk) * 128 + c];
        else         v = (l ? Wc1 : Wc0)[(size_t)(kt * 128 + kk) * 64 + (c - 128)];
        __nv_bfloat16 hi = __float2bfloat16(v);
        __nv_bfloat16 lo = __float2bfloat16(v - __bfloat162float(hi));
        unsigned char* base = d_WI + l * 245760;
        *(__nv_bfloat16*)(base + kcat * 384 + c * 2) = hi;
        *(__nv_bfloat16*)(base + 122880 + kcat * 384 + c * 2) = lo;
    }
}

// ---------------------------------------------------------------------------
// WMMA precompute of Gx/Cx — 512-thread version (16 warps, better latency
// hiding; same smem/math as R14). Phase1: warp = 1 row-tile x 4 col-tiles.
// Phase2: warp = 1 row-tile x 3 col-tiles.
// ---------------------------------------------------------------------------
#define PRE2_SMEM (83968 + 102400)

__global__ void __launch_bounds__(512, 1)
pre_wmma(const float* __restrict__ Xin, const float* __restrict__ bg,
         const float* __restrict__ bc, int layer)
{
    unsigned char* sm  = (unsigned char*)smem;
    __nv_bfloat16* A2h = (__nv_bfloat16*)sm;
    __nv_bfloat16* A2l = (__nv_bfloat16*)(sm + 41984);
    unsigned char* SCR = sm + 83968;

    const int tid = threadIdx.x;
    const int w = tid >> 5;
    const int bt = blockIdx.x;

    for (int i = tid; i < 4096; i += 512) {
        int prec = i >> 11, r2 = i & 2047, row = r2 >> 3, c = r2 & 7;
        cp16(SCR + prec * 36864 + row * 144 + c * 16,
             d_MI + prec * 32768 + row * 128 + c * 16);
    }
    CP_COMMIT();
    const float* xsrc = (layer ? d_out0 : Xin) + (size_t)bt * 4096;
    for (int i = tid; i < 4096; i += 512) {
        int n = i >> 6, f = i & 63;
        float v = xsrc[i];
        __nv_bfloat16 hi = __float2bfloat16(v);
        __nv_bfloat16 lo = __float2bfloat16(v - __bfloat162float(hi));
        A2h[n * 328 + f] = hi;
        A2l[n * 328 + f] = lo;
    }
    CP_WAIT0();
    __syncthreads();

    // phase 1: xa = M_stack(256x64) @ x(64x64); warp w: row-tile w, 4 col-tiles
    {
        wmma::fragment<wmma::accumulator, 16, 16, 16, float> acc1[4];
        #pragma unroll
        for (int i = 0; i < 4; ++i) wmma::fill_fragment(acc1[i], 0.f);
        const __nv_bfloat16* Mh = (const __nv_bfloat16*)SCR;
        const __nv_bfloat16* Ml = (const __nv_bfloat16*)(SCR + 36864);
        #pragma unroll
        for (int ks = 0; ks < 4; ++ks) {
            wmma::fragment<wmma::matrix_a, 16, 16, 16, __nv_bfloat16, wmma::row_major> ah, al;
            wmma::load_matrix_sync(ah, Mh + w * 16 * 72 + ks * 16, 72);
            wmma::load_matrix_sync(al, Ml + w * 16 * 72 + ks * 16, 72);
            #pragma unroll
            for (int nt = 0; nt < 4; ++nt) {
                wmma::fragment<wmma::matrix_b, 16, 16, 16, __nv_bfloat16, wmma::row_major> bh, bl;
                wmma::load_matrix_sync(bh, A2h + ks * 16 * 328 + nt * 16, 328);
                wmma::load_matrix_sync(bl, A2l + ks * 16 * 328 + nt * 16, 328);
                wmma::mma_sync(acc1[nt], ah, bh, acc1[nt]);
                wmma::mma_sync(acc1[nt], al, bh, acc1[nt]);
                wmma::mma_sync(acc1[nt], ah, bl, acc1[nt]);
            }
        }
        __syncthreads();                 // M reads done -> S may overwrite
        float* S = (float*)SCR;          // 256 x 72 fp32
        #pragma unroll
        for (int nt = 0; nt < 4; ++nt)
            wmma::store_matrix_sync(S + w * 16 * 72 + nt * 16, acc1[nt], 72,
                                    wmma::mem_row_major);
        __syncthreads();
        for (int i = tid; i < 16384; i += 512) {
            int row = i >> 6, f = i & 63;
            int k = row >> 6, m = row & 63;
            float v = S[row * 72 + f];
            __nv_bfloat16 hi = __float2bfloat16(v);
            __nv_bfloat16 lo = __float2bfloat16(v - __bfloat162float(hi));
            A2h[m * 328 + (k + 1) * 64 + f] = hi;
            A2l[m * 328 + (k + 1) * 64 + f] = lo;
        }
        __syncthreads();
    }

    // phase 2: [x|xa](64x320) @ WI(320x192); warp w: row-tile w>>2, col-tiles (w&3)*3+{0..2}
    {
        wmma::fragment<wmma::accumulator, 16, 16, 16, float> acc2[3];
        #pragma unroll
        for (int i = 0; i < 3; ++i) wmma::fill_fragment(acc2[i], 0.f);
        const int mt = w >> 2, ncg = (w & 3) * 3;
        const unsigned char* gW = d_WI + layer * 245760;

        {
            unsigned char* dst = SCR;
            for (int i = tid; i < 1536; i += 512) {
                int row = i / 24, c = i % 24;
                cp16(dst + row * 400 + c * 16, gW + row * 384 + c * 16);
                cp16(dst + 25600 + row * 400 + c * 16, gW + 122880 + row * 384 + c * 16);
            }
            CP_COMMIT();
        }

        for (int kt = 0; kt < 5; ++kt) {
            if (kt < 4) {
                unsigned char* dst = SCR + ((kt + 1) & 1) * 51200;
                const unsigned char* srcH = gW + (kt + 1) * 24576;
                const unsigned char* srcL = gW + 122880 + (kt + 1) * 24576;
                for (int i = tid; i < 1536; i += 512) {
                    int row = i / 24, c = i % 24;
                    cp16(dst + row * 400 + c * 16, srcH + row * 384 + c * 16);
                    cp16(dst + 25600 + row * 400 + c * 16, srcL + row * 384 + c * 16);
                }
            }
            CP_COMMIT();
            CP_WAIT1();
            __syncthreads();

            const __nv_bfloat16* WbH = (const __nv_bfloat16*)(SCR + (kt & 1) * 51200);
            const __nv_bfloat16* WbL = (const __nv_bfloat16*)(SCR + (kt & 1) * 51200 + 25600);
            #pragma unroll
            for (int ks = 0; ks < 4; ++ks) {
                wmma::fragment<wmma::matrix_a, 16, 16, 16, __nv_bfloat16, wmma::row_major> ah, al;
                wmma::load_matrix_sync(ah, A2h + mt * 16 * 328 + kt * 64 + ks * 16, 328);
                wmma::load_matrix_sync(al, A2l + mt * 16 * 328 + kt * 64 + ks * 16, 328);
                #pragma unroll
                for (int nt = 0; nt < 3; ++nt) {
                    wmma::fragment<wmma::matrix_b, 16, 16, 16, __nv_bfloat16, wmma::row_major> bh, bl;
                    int nc = (ncg + nt) * 16;
                    wmma::load_matrix_sync(bh, WbH + ks * 16 * 200 + nc, 200);
                    wmma::load_matrix_sync(bl, WbL + ks * 16 * 200 + nc, 200);
                    wmma::mma_sync(acc2[nt], ah, bh, acc2[nt]);
                    wmma::mma_sync(acc2[nt], al, bh, acc2[nt]);
                    wmma::mma_sync(acc2[nt], ah, bl, acc2[nt]);
                }
            }
            __syncthreads();
        }

        float* S = (float*)SCR;          // 64 x 200 fp32
        #pragma unroll
        for (int nt = 0; nt < 3; ++nt)
            wmma::store_matrix_sync(S + mt * 16 * 200 + (ncg + nt) * 16,
                                    acc2[nt], 200, wmma::mem_row_major);
        __syncthreads();
        for (int i = tid; i < 12288; i += 512) {
            int n = i / 192, c = i % 192;
            float v = S[n * 200 + c];
            if (c < 128) d_Gx[(size_t)bt * 8192 + n * 128 + c] = v + bg[c];
            else         d_Cx[(size_t)bt * 4096 + n * 64 + (c - 128)] = v + bc[c - 128];
        }
    }
}

// ---------------------------------------------------------------------------
// Scan v7 (R15, proven): wmma V-phases, fp32 k-split M-applies.
// ---------------------------------------------------------------------------
#define SCAN_SMEM_BYTES 223232

__global__ void __launch_bounds__(512, 1) __cluster_dims__(4, 1, 1)
scan_kernel(const float* __restrict__ Wg, const float* __restrict__ Wc,
            const int* __restrict__ lens, int layer)
{
    unsigned char* sm = (unsigned char*)smem;
    __nv_bfloat16* WIh = (__nv_bfloat16*)sm;
    __nv_bfloat16* WIl = (__nv_bfloat16*)(sm + 33792);
    float* Ms    = (float*)(sm + 67584);
    float* Vs    = (float*)(sm + 137216);
    __nv_bfloat16* hH = (__nv_bfloat16*)(sm + 179200);
    __nv_bfloat16* hL = (__nv_bfloat16*)(sm + 188416);
    float* h_loc = (float*)(sm + 197632);
    float* rst   = (float*)(sm + 201984);
    float* ugs   = (float*)(sm + 206336);
    float* hst   = (float*)(sm + 210688);
    float* yP    = (float*)(sm + 215040);

    const int tid = threadIdx.x;
    const int w   = tid >> 5;
    const int b = blockIdx.x >> 2;
    const int j = blockIdx.x & 3;

    for (int i = tid; i < 64 * 240; i += 512) {
        int d = i / 240, o = i % 240;
        float v;
        if (o < 160) {
            int k = o >> 5, c = o & 31;
            int g = (c < 16) ? (j * 16 + c) : (64 + j * 16 + (c - 16));
            v = Wg[(size_t)(k * 128 + 64 + d) * 128 + g];
        } else {
            int oc = o - 160, k = oc >> 4, c = oc & 15;
            v = Wc[(size_t)(k * 128 + 64 + d) * 64 + j * 16 + c];
        }
        __nv_bfloat16 hi = __float2bfloat16(v);
        __nv_bfloat16 lo = __float2bfloat16(v - __bfloat162float(hi));
        WIh[d * 264 + o] = hi;
        WIl[d * 264 + o] = lo;
    }
    for (int i = tid; i < 16384; i += 512) {
        int k = i >> 12, r = (i >> 6) & 63, p = i & 63;
        Ms[k * 4352 + r * 68 + p] = d_M[i];
    }
    for (int i = tid; i < 4096; i += 512) {
        int n = i >> 6, d = i & 63;
        hH[n * 72 + d] = __float2bfloat16(0.f);
        hL[n * 72 + d] = __float2bfloat16(0.f);
        if (d < 17) h_loc[n * 17 + d] = 0.f;
    }

    int idx_t = lens[b] - 1;
    idx_t = idx_t < 0 ? 0 : (idx_t > T_ - 1 ? T_ - 1 : idx_t);

    uint32_t rbase[4], hbase[4];
    #pragma unroll
    for (int r = 0; r < 4; ++r) {
        rbase[r] = mapa_rank(s_u32(rst), (uint32_t)r);
        hbase[r] = mapa_rank(s_u32(hst), (uint32_t)r);
    }

    const int dh  = tid >> 8;
    const int s5  = tid & 255;
    const int mg  = s5 >> 3;
    const int ja4 = (s5 & 7) * 4;
    const int ja2 = (s5 & 7) * 2;
    const int g0  = (ja4 < 16) ? (j * 16 + ja4) : (64 + j * 16 + (ja4 - 16));
    const int c0  = j * 16 + ja2;
    const u64t ONE = pack_dup(1.f);
    const int en0 = tid >> 4, edl = tid & 15;
    const uint32_t eoff0 = (uint32_t)(en0 * 17 + edl) * 4;
    const uint32_t eoff1 = (uint32_t)((en0 + 32) * 17 + edl) * 4;
    const int rt = w & 3;

    const float* gxb = d_Gx + (size_t)b * T_ * 8192;
    const float* cxb = d_Cx + (size_t)b * T_ * 4096;

    for (int t = 0; t < T_; ++t) {
        __syncthreads();

        float4 gA = make_float4(0.f, 0.f, 0.f, 0.f);
        float4 gB = gA;
        float2 cA = make_float2(0.f, 0.f);
        float2 cB = cA;
        if (dh == 0) {
            const float* gx = gxb + (size_t)t * 8192;
            const float* cx = cxb + (size_t)t * 4096;
            gA = __ldg((const float4*)(gx + mg * 128 + g0));
            gB = __ldg((const float4*)(gx + (mg + 32) * 128 + g0));
            cA = __ldg((const float2*)(cx + mg * 64 + c0));
            cB = __ldg((const float2*)(cx + (mg + 32) * 64 + c0));
        }

        // gate V-phase wmma
        {
            wmma::fragment<wmma::matrix_a, 16, 16, 16, __nv_bfloat16, wmma::row_major> a_h[4], a_l[4];
            #pragma unroll
            for (int kf = 0; kf < 4; ++kf) {
                wmma::load_matrix_sync(a_h[kf], hH + rt * 16 * 72 + kf * 16, 72);
                wmma::load_matrix_sync(a_l[kf], hL + rt * 16 * 72 + kf * 16, 72);
            }
            for (int tile = w; tile < 40; tile += 16) {
                int ct = tile >> 2;
                wmma::fragment<wmma::accumulator, 16, 16, 16, float> acc;
                wmma::fill_fragment(acc, 0.f);
                #pragma unroll
                for (int kf = 0; kf < 4; ++kf) {
                    wmma::fragment<wmma::matrix_b, 16, 16, 16, __nv_bfloat16, wmma::row_major> bh, bl;
                    wmma::load_matrix_sync(bh, WIh + kf * 16 * 264 + ct * 16, 264);
                    wmma::load_matrix_sync(bl, WIl + kf * 16 * 264 + ct * 16, 264);
                    wmma::mma_sync(acc, a_h[kf], bh, acc);
                    wmma::mma_sync(acc, a_l[kf], bh, acc);
                    wmma::mma_sync(acc, a_h[kf], bl, acc);
                }
                wmma::store_matrix_sync(Vs + rt * 16 * 164 + ct * 16, acc, 164, wmma::mem_row_major);
            }
        }
        __syncthreads();

        // gate M-apply (k-split) + sigmoid + stage
        {
            u64t y00, y01, y10, y11;
            if (dh == 0) {
                float4 vA = *(const float4*)(Vs + mg * 164 + ja4);
                float4 vB = *(const float4*)(Vs + (mg + 32) * 164 + ja4);
                y00 = pack2(gA.x + vA.x, gA.y + vA.y);
                y01 = pack2(gA.z + vA.z, gA.w + vA.w);
                y10 = pack2(gB.x + vB.x, gB.y + vB.y);
                y11 = pack2(gB.z + vB.z, gB.w + vB.w);
            } else {
                y00 = y01 = y10 = y11 = pack_dup(0.f);
            }
            const int kb = 1 + dh * 2;
            #pragma unroll
            for (int kk = 0; kk < 2; ++kk) {
                const float* Mk = Ms + (kb - 1 + kk) * 4352;
                const float* Vk = Vs + (kb + kk) * 32;
                #pragma unroll 4
                for (int m = 0; m < 64; m += 4) {
                    float4 mA = *(const float4*)(Mk + mg * 68 + m);
                    float4 mB = *(const float4*)(Mk + (mg + 32) * 68 + m);
                    float mAa[4] = {mA.x, mA.y, mA.z, mA.w};
                    float mBa[4] = {mB.x, mB.y, mB.z, mB.w};
                    #pragma unroll
                    for (int q = 0; q < 4; ++q) {
                        ulonglong2 v = *(const ulonglong2*)(Vk + (m + q) * 164 + ja4);
                        u64t da = pack_dup(mAa[q]);
                        u64t db = pack_dup(mBa[q]);
                        fma2(y00, da, v.x); fma2(y01, da, v.y);
                        fma2(y10, db, v.x); fma2(y11, db, v.y);
                    }
                }
            }
            if (dh == 1) {
                ulonglong2 sv;
                sv.x = y00; sv.y = y01; *(ulonglong2*)(yP + s5 * 8)     = sv;
                sv.x = y10; sv.y = y11; *(ulonglong2*)(yP + s5 * 8 + 4) = sv;
            }
            __syncthreads();
            if (dh == 0) {
                ulonglong2 pa = *(const ulonglong2*)(yP + s5 * 8);
                ulonglong2 pb = *(const ulonglong2*)(yP + s5 * 8 + 4);
                fma2(y00, ONE, pa.x); fma2(y01, ONE, pa.y);
                fma2(y10, ONE, pb.x); fma2(y11, ONE, pb.y);
                float2 p00 = unpack2(y00), p01 = unpack2(y01);
                float2 p10 = unpack2(y10), p11 = unpack2(y11);
                float v0a[4] = {p00.x, p00.y, p01.x, p01.y};
                float v1a[4] = {p10.x, p10.y, p11.x, p11.y};
                #pragma unroll
                for (int q = 0; q < 4; ++q) {
                    int c = ja4 + q;
                    float s0 = sigmoid_f(v0a[q]);
                    float s1 = sigmoid_f(v1a[q]);
                    if (c < 16) { rst[mg * 17 + c] = s0;        rst[(mg + 32) * 17 + c] = s1; }
                    else        { ugs[mg * 17 + c - 16] = s0;   ugs[(mg + 32) * 17 + c - 16] = s1; }
                }
            }
        }

        // r exchange; rh = r*(hH+hL) back into hH/hL split
        CLUSTER_ARRIVE();
        __syncthreads();
        {
            int d = j * 16 + edl;
            #pragma unroll
            for (int half = 0; half < 2; ++half) {
                int n = en0 + half * 32;
                float hv = __bfloat162float(hH[n * 72 + d]) + __bfloat162float(hL[n * 72 + d]);
                float rh = rst[n * 17 + edl] * hv;
                __nv_bfloat16 hi = __float2bfloat16(rh);
                hH[n * 72 + d] = hi;
                hL[n * 72 + d] = __float2bfloat16(rh - __bfloat162float(hi));
            }
        }
        CLUSTER_WAIT();
        {
            float rv[3][2];
            #pragma unroll
            for (int rr = 1; rr < 4; ++rr) {
                uint32_t rb = rbase[(j + rr) & 3];
                rv[rr - 1][0] = ldc_f32(rb + eoff0);
                rv[rr - 1][1] = ldc_f32(rb + eoff1);
            }
            #pragma unroll
            for (int rr = 1; rr < 4; ++rr) {
                int d = ((j + rr) & 3) * 16 + edl;
                #pragma unroll
                for (int half = 0; half < 2; ++half) {
                    int n = en0 + half * 32;
                    float hv = __bfloat162float(hH[n * 72 + d]) + __bfloat162float(hL[n * 72 + d]);
                    float rh = rv[rr - 1][half] * hv;
                    __nv_bfloat16 hi = __float2bfloat16(rh);
                    hH[n * 72 + d] = hi;
                    hL[n * 72 + d] = __float2bfloat16(rh - __bfloat162float(hi));
                }
            }
        }
        __syncthreads();

        // cand V-phase wmma
        {
            wmma::fragment<wmma::matrix_a, 16, 16, 16, __nv_bfloat16, wmma::row_major> a_h[4], a_l[4];
            #pragma unroll
            for (int kf = 0; kf < 4; ++kf) {
                wmma::load_matrix_sync(a_h[kf], hH + rt * 16 * 72 + kf * 16, 72);
                wmma::load_matrix_sync(a_l[kf], hL + rt * 16 * 72 + kf * 16, 72);
            }
            for (int tile = w; tile < 20; tile += 16) {
                int ct = tile >> 2;
                wmma::fragment<wmma::accumulator, 16, 16, 16, float> acc;
                wmma::fill_fragment(acc, 0.f);
                #pragma unroll
                for (int kf = 0; kf < 4; ++kf) {
                    wmma::fragment<wmma::matrix_b, 16, 16, 16, __nv_bfloat16, wmma::row_major> bh, bl;
                    wmma::load_matrix_sync(bh, WIh + kf * 16 * 264 + 160 + ct * 16, 264);
                    wmma::load_matrix_sync(bl, WIl + kf * 16 * 264 + 160 + ct * 16, 264);
                    wmma::mma_sync(acc, a_h[kf], bh, acc);
                    wmma::mma_sync(acc, a_l[kf], bh, acc);
                    wmma::mma_sync(acc, a_h[kf], bl, acc);
                }
                wmma::store_matrix_sync(Vs + rt * 16 * 164 + ct * 16, acc, 164, wmma::mem_row_major);
            }
        }
        __syncthreads();

        // cand M-apply (k-split) + GRU update
        {
            u64t y0, y1;
            if (dh == 0) {
                float2 v0 = *(const float2*)(Vs + mg * 164 + ja2);
                float2 v1 = *(const float2*)(Vs + (mg + 32) * 164 + ja2);
                y0 = pack2(cA.x + v0.x, cA.y + v0.y);
                y1 = pack2(cB.x + v1.x, cB.y + v1.y);
            } else {
                y0 = y1 = pack_dup(0.f);
            }
            const int kb = 1 + dh * 2;
            #pragma unroll
            for (int kk = 0; kk < 2; ++kk) {
                const float* Mk = Ms + (kb - 1 + kk) * 4352;
                const float* Vk = Vs + (kb + kk) * 16;
                #pragma unroll 4
                for (int m = 0; m < 64; m += 4) {
                    float4 mA = *(const float4*)(Mk + mg * 68 + m);
                    float4 mB = *(const float4*)(Mk + (mg + 32) * 68 + m);
                    float mAa[4] = {mA.x, mA.y, mA.z, mA.w};
                    float mBa[4] = {mB.x, mB.y, mB.z, mB.w};
                    #pragma unroll
                    for (int q = 0; q < 4; ++q) {
                        u64t v = *(const u64t*)(Vk + (m + q) * 164 + ja2);
                        fma2(y0, pack_dup(mAa[q]), v);
                        fma2(y1, pack_dup(mBa[q]), v);
                    }
                }
            }
            if (dh == 1) {
                *(u64t*)(yP + s5 * 4)     = y0;
                *(u64t*)(yP + s5 * 4 + 2) = y1;
            }
            __syncthreads();
            if (dh == 0) {
                u64t pa = *(const u64t*)(yP + s5 * 4);
                u64t pb = *(const u64t*)(yP + s5 * 4 + 2);
                fma2(y0, ONE, pa);
                fma2(y1, ONE, pb);
                float* hout0 = d_out0 + ((size_t)(b * T_ + t)) * 4096;
                float2 cc0 = unpack2(y0), cc1 = unpack2(y1);
                float cand0[2] = {cc0.x, cc0.y};
                float cand1[2] = {cc1.x, cc1.y};
                #pragma unroll
                for (int q = 0; q < 2; ++q) {
                    int cl = ja2 + q;
                    int col = j * 16 + cl;
                    float cv0 = tanh_f(cand0[q]);
                    float ug0 = ugs[mg * 17 + cl];
                    float hn0 = ug0 * h_loc[mg * 17 + cl] + (1.f - ug0) * cv0;
                    hst[mg * 17 + cl] = hn0;
                    float cv1 = tanh_f(cand1[q]);
                    float ug1 = ugs[(mg + 32) * 17 + cl];
                    float hn1 = ug1 * h_loc[(mg + 32) * 17 + cl] + (1.f - ug1) * cv1;
                    hst[(mg + 32) * 17 + cl] = hn1;
                    if (layer == 0) {
                        hout0[mg * 64 + col]        = hn0;
                        hout0[(mg + 32) * 64 + col] = hn1;
                    } else if (t == idx_t) {
                        d_last[(size_t)b * 4096 + mg * 64 + col]        = hn0;
                        d_last[(size_t)b * 4096 + (mg + 32) * 64 + col] = hn1;
                    }
                }
            }
        }

        // h exchange
        CLUSTER_ARRIVE();
        __syncthreads();
        {
            int d = j * 16 + edl;
            #pragma unroll
            for (int half = 0; half < 2; ++half) {
                int n = en0 + half * 32;
                float hv = hst[n * 17 + edl];
                __nv_bfloat16 hi = __float2bfloat16(hv);
                hH[n * 72 + d] = hi;
                hL[n * 72 + d] = __float2bfloat16(hv - __bfloat162float(hi));
                h_loc[n * 17 + edl] = hv;
            }
        }
        CLUSTER_WAIT();
        {
            float hv[3][2];
            #pragma unroll
            for (int rr = 1; rr < 4; ++rr) {
                uint32_t hb = hbase[(j + rr) & 3];
                hv[rr - 1][0] = ldc_f32(hb + eoff0);
                hv[rr - 1][1] = ldc_f32(hb + eoff1);
            }
            #pragma unroll
            for (int rr = 1; rr < 4; ++rr) {
                int d = ((j + rr) & 3) * 16 + edl;
                #pragma unroll
                for (int half = 0; half < 2; ++half) {
                    int n = en0 + half * 32;
                    float v = hv[rr - 1][half];
                    __nv_bfloat16 hi = __float2bfloat16(v);
                    hH[n * 72 + d] = hi;
                    hL[n * 72 + d] = __float2bfloat16(v - __bfloat162float(hi));
                }
            }
        }
    }
    CLUSTER_SYNC();
}

// ---------------------------------------------------------------------------
__global__ void final_kernel(const float* __restrict__ Wp, const float* __restrict__ bp,
                             float* __restrict__ out)
{
    __shared__ float red[64 * 4];
    const int b = blockIdx.x, n = threadIdx.x;
    const float* h = d_last + (size_t)b * 4096 + n * 64;
    float l0 = bp[0], l1 = bp[1], l2 = bp[2], l3 = bp[3];
    #pragma unroll 8
    for (int d = 0; d < 64; ++d) {
        float v = fmaxf(h[d], 0.f);
        l0 += v * Wp[d * 4 + 0];
        l1 += v * Wp[d * 4 + 1];
        l2 += v * Wp[d * 4 + 2];
        l3 += v * Wp[d * 4 + 3];
    }
    red[n * 4 + 0] = l0; red[n * 4 + 1] = l1; red[n * 4 + 2] = l2; red[n * 4 + 3] = l3;
    __syncthreads();
    for (int s = 32; s > 0; s >>= 1) {
        if (n < s) {
            #pragma unroll
            for (int c = 0; c < 4; ++c)
                red[n * 4 + c] = fmaxf(red[n * 4 + c], red[(n + s) * 4 + c]);
        }
        __syncthreads();
    }
    if (n < 4) out[b * 4 + n] = red[n];
}

// ---------------------------------------------------------------------------
extern "C" void kernel_launch(void* const* d_in, const int* in_sizes, int n_in,
                              void* d_out, int out_size)
{
    (void)in_sizes; (void)n_in; (void)out_size;
    const float* X   = (const float*)d_in[0];
    const int*   len = (const int*)  d_in[1];
    const float* S0  = (const float*)d_in[2];
    const float* S1  = (const float*)d_in[3];
    const float* Wg0 = (const float*)d_in[4];
    const float* bg0 = (const float*)d_in[5];
    const float* Wc0 = (const float*)d_in[6];
    const float* bc0 = (const float*)d_in[7];
    const float* Wg1 = (const float*)d_in[8];
    const float* bg1 = (const float*)d_in[9];
    const float* Wc1 = (const float*)d_in[10];
    const float* bc1 = (const float*)d_in[11];
    const float* Wp  = (const float*)d_in[12];
    const float* bp  = (const float*)d_in[13];
    float* out = (float*)d_out;

    cudaFuncSetAttribute(pre_wmma,    cudaFuncAttributeMaxDynamicSharedMemorySize, PRE2_SMEM);
    cudaFuncSetAttribute(scan_kernel, cudaFuncAttributeMaxDynamicSharedMemorySize, SCAN_SMEM_BYTES);

    prep_kernel<<<2, 256>>>(S0, S1);
    prep_img<<<64, 256>>>(Wg0, Wc0, Wg1, Wc1);
    pre_wmma<<<B_ * T_, 512, PRE2_SMEM>>>(X, bg0, bc0, 0);
    scan_kernel<<<128, 512, SCAN_SMEM_BYTES>>>(Wg0, Wc0, len, 0);
    pre_wmma<<<B_ * T_, 512, PRE2_SMEM>>>(X, bg1, bc1, 1);
    scan_kernel<<<128, 512, SCAN_SMEM_BYTES>>>(Wg1, Wc1, len, 1);
    final_kernel<<<B_, 64>>>(Wp, bp, out);
}